// round 13
// baseline (speedup 1.0000x reference)
#include <cuda_runtime.h>
#include <cuda.h>
#include <cuda_bf16.h>
#include <cstdint>
#include <dlfcn.h>

// HighOrderActivation: simplex interpolation over K=4 corners of a 2^4 table.
// X: [B=1024, D=512, 4] f32, params: [D=512, 16, 64] f32, out: [B, D, 64] f32.
//
// R12 post-mortem: kernel sits exactly at the LSU floor:
//   (7 LDS.128 x 4cyc + 2 STG.128 x 12cyc) = 52 LSU cyc / 4 output rows = 26us.
// This round removes the STG cost from the LSU: results are STS'd into a smem
// staging buffer (4 cyc each) and drained by ONE 3D TMA store per block
// (UTMASTG on the TMA engine). New floor: 36 cyc / 4 rows ≈ 18-20us.
// cuTensorMapEncodeTiled is resolved via dlopen(libcuda) at launch time (pure
// host work, capture-safe); if unavailable, fall back to the proven STG kernel.

#define B_DIM  1024
#define D_DIM  512
#define TBL_ROWS 16

// ---------- common branchless sort helpers ----------
static __device__ __forceinline__ uint32_t fkey(float f, uint32_t i) {
    uint32_t u = __float_as_uint(f);
    uint32_t m = (uint32_t)((int32_t)u >> 31);          // ~0 if negative
    uint32_t k = u ^ (m | 0x80000000u);
    return (k & ~3u) | i;
}
static __device__ __forceinline__ float fdec(uint32_t k) {
    uint32_t kc = k & ~3u;
    uint32_t m  = (uint32_t)((int32_t)kc >> 31);        // ~0 if originally >= 0
    return __uint_as_float(kc ^ (~m | 0x80000000u));
}

#define USWAP(a, b_)                                   \
    do {                                               \
        uint32_t lo = min(a, b_);                      \
        uint32_t hi = max(a, b_);                      \
        a = lo; b_ = hi;                               \
    } while (0)

// Shared per-pair computation: from xv produce coefficients and corner rows.
static __device__ __forceinline__ void simplex_coef(
    float4 xv, float& c0, float& c1, float& c2, float& c3,
    int& ind1, int& ind2, int& ind3)
{
    uint32_t k0 = fkey(xv.x, 0), k1 = fkey(xv.y, 1);
    uint32_t k2 = fkey(xv.z, 2), k3 = fkey(xv.w, 3);
    USWAP(k0, k1); USWAP(k2, k3); USWAP(k0, k2); USWAP(k1, k3); USWAP(k1, k2);
    const float v0 = fdec(k0), v1 = fdec(k1), v2 = fdec(k2), v3 = fdec(k3);
    const int i0 = (int)(k0 & 3u), i1 = (int)(k1 & 3u), i3 = (int)(k3 & 3u);
    ind1 = 15 - (1 << i0);
    ind2 = ind1 - (1 << i1);
    ind3 = (1 << i3);
    c0 = v0; c1 = v1 - v0; c2 = v2 - v1; c3 = v3 - v2;
}

// ============================================================
// TMA-store kernel: BCHUNK=64 b's per block, one d per block.
// ============================================================
#define T_BCHUNK 64
#define T_THREADS 256
#define T_PAIRS_PER_ITER (T_THREADS / 8)   // 32
#define T_ITERS (T_BCHUNK / T_PAIRS_PER_ITER)  // 2

__global__ __launch_bounds__(T_THREADS)
void hoa_tma_kernel(const float* __restrict__ X,
                    const float* __restrict__ params,
                    const __grid_constant__ CUtensorMap tmap)
{
    __shared__ float4 tab[TBL_ROWS * 16];                  // 4 KB
    __shared__ float4 xsm[T_BCHUNK];                       // 1 KB
    __shared__ __align__(128) float4 obuf[T_BCHUNK * 16];  // 16 KB staging

    const int tid = threadIdx.x;
    const int d   = blockIdx.y;
    const int b0  = blockIdx.x * T_BCHUNK;

    tab[tid] = reinterpret_cast<const float4*>(params)[(size_t)d * (TBL_ROWS * 16) + tid];
    if (tid < T_BCHUNK) {
        xsm[tid] = reinterpret_cast<const float4*>(X)[(size_t)(b0 + tid) * D_DIM + d];
    }
    __syncthreads();

    const int o         = tid & 7;    // float4 slots o and o+8
    const int pair_base = tid >> 3;   // 0..31

    const float4 r15a = tab[15 * 16 + o];
    const float4 r15b = tab[15 * 16 + o + 8];

    #pragma unroll
    for (int it = 0; it < T_ITERS; ++it) {
        const int pr = it * T_PAIRS_PER_ITER + pair_base;

        const float4 xv = xsm[pr];
        float c0, c1, c2, c3; int ind1, ind2, ind3;
        simplex_coef(xv, c0, c1, c2, c3, ind1, ind2, ind3);

        const float4 g1a = tab[ind1 * 16 + o];
        const float4 g1b = tab[ind1 * 16 + o + 8];
        const float4 g2a = tab[ind2 * 16 + o];
        const float4 g2b = tab[ind2 * 16 + o + 8];
        const float4 g3a = tab[ind3 * 16 + o];
        const float4 g3b = tab[ind3 * 16 + o + 8];

        float4 ra, rb;
        ra.x = c0 * r15a.x + c1 * g1a.x + c2 * g2a.x + c3 * g3a.x;
        ra.y = c0 * r15a.y + c1 * g1a.y + c2 * g2a.y + c3 * g3a.y;
        ra.z = c0 * r15a.z + c1 * g1a.z + c2 * g2a.z + c3 * g3a.z;
        ra.w = c0 * r15a.w + c1 * g1a.w + c2 * g2a.w + c3 * g3a.w;
        rb.x = c0 * r15b.x + c1 * g1b.x + c2 * g2b.x + c3 * g3b.x;
        rb.y = c0 * r15b.y + c1 * g1b.y + c2 * g2b.y + c3 * g3b.y;
        rb.z = c0 * r15b.z + c1 * g1b.z + c2 * g2b.z + c3 * g3b.z;
        rb.w = c0 * r15b.w + c1 * g1b.w + c2 * g2b.w + c3 * g3b.w;

        // STS.128 x2 into the staging buffer (crossbar: 4 cyc each, off the
        // STG issue path). Row pr occupies bytes [pr*256, pr*256+256).
        obuf[pr * 16 + o]     = ra;
        obuf[pr * 16 + o + 8] = rb;
    }

    // Make generic-proxy smem writes visible to the async (TMA) proxy.
    asm volatile("fence.proxy.async.shared::cta;" ::: "memory");
    __syncthreads();

    if (tid == 0) {
        uint32_t saddr;
        asm("{ .reg .u64 t; cvta.to.shared.u64 t, %1; cvt.u32.u64 %0, t; }"
            : "=r"(saddr) : "l"((const void*)obuf));
        // One 16 KB 3D TMA store: box (64 f32, 1 d, 64 b), coords (0, d, b0).
        asm volatile(
            "cp.async.bulk.tensor.3d.global.shared::cta.tile.bulk_group "
            "[%0, {%1, %2, %3}], [%4];"
            :: "l"(&tmap), "r"(0), "r"(d), "r"(b0), "r"(saddr)
            : "memory");
        asm volatile("cp.async.bulk.commit_group;" ::: "memory");
        // Wait until smem has been READ by the TMA engine (write completion
        // is guaranteed by kernel-boundary semantics) so smem reuse by the
        // next CTA on this SM is safe.
        asm volatile("cp.async.bulk.wait_group.read 0;" ::: "memory");
    }
    __syncthreads();
}

// ============================================================
// Fallback kernel (proven R12 path, direct STG): BCHUNK=128.
// ============================================================
#define F_BCHUNK 128
#define F_THREADS 256
#define F_PAIRS_PER_ITER (F_THREADS / 8)   // 32
#define F_ITERS (F_BCHUNK / F_PAIRS_PER_ITER)  // 4

__global__ __launch_bounds__(F_THREADS, 6)
void hoa_kernel(const float* __restrict__ X,
                const float* __restrict__ params,
                float* __restrict__ out)
{
    __shared__ float4 tab[TBL_ROWS * 16];
    __shared__ float4 xsm[F_BCHUNK];

    const int tid = threadIdx.x;
    const int d   = blockIdx.y;
    const int b0  = blockIdx.x * F_BCHUNK;

    tab[tid] = reinterpret_cast<const float4*>(params)[(size_t)d * (TBL_ROWS * 16) + tid];
    if (tid < F_BCHUNK) {
        xsm[tid] = reinterpret_cast<const float4*>(X)[(size_t)(b0 + tid) * D_DIM + d];
    }
    __syncthreads();

    const int o         = tid & 7;
    const int pair_base = tid >> 3;

    const float4 r15a = tab[15 * 16 + o];
    const float4 r15b = tab[15 * 16 + o + 8];

    #pragma unroll
    for (int it = 0; it < F_ITERS; ++it) {
        const int pr = it * F_PAIRS_PER_ITER + pair_base;
        const size_t p = (size_t)(b0 + pr) * D_DIM + d;

        const float4 xv = xsm[pr];
        float c0, c1, c2, c3; int ind1, ind2, ind3;
        simplex_coef(xv, c0, c1, c2, c3, ind1, ind2, ind3);

        const float4 g1a = tab[ind1 * 16 + o];
        const float4 g1b = tab[ind1 * 16 + o + 8];
        const float4 g2a = tab[ind2 * 16 + o];
        const float4 g2b = tab[ind2 * 16 + o + 8];
        const float4 g3a = tab[ind3 * 16 + o];
        const float4 g3b = tab[ind3 * 16 + o + 8];

        float4 ra, rb;
        ra.x = c0 * r15a.x + c1 * g1a.x + c2 * g2a.x + c3 * g3a.x;
        ra.y = c0 * r15a.y + c1 * g1a.y + c2 * g2a.y + c3 * g3a.y;
        ra.z = c0 * r15a.z + c1 * g1a.z + c2 * g2a.z + c3 * g3a.z;
        ra.w = c0 * r15a.w + c1 * g1a.w + c2 * g2a.w + c3 * g3a.w;
        rb.x = c0 * r15b.x + c1 * g1b.x + c2 * g2b.x + c3 * g3b.x;
        rb.y = c0 * r15b.y + c1 * g1b.y + c2 * g2b.y + c3 * g3b.y;
        rb.z = c0 * r15b.z + c1 * g1b.z + c2 * g2b.z + c3 * g3b.z;
        rb.w = c0 * r15b.w + c1 * g1b.w + c2 * g2b.w + c3 * g3b.w;

        float4* orow = reinterpret_cast<float4*>(out) + p * 16;
        orow[o]     = ra;
        orow[o + 8] = rb;
    }
}

// ============================================================
// Host: build tensor map via dlopen'd libcuda; fall back if absent.
// ============================================================
typedef CUresult (*EncodeTiledFn)(
    CUtensorMap*, CUtensorMapDataType, cuuint32_t, void*,
    const cuuint64_t*, const cuuint64_t*, const cuuint32_t*, const cuuint32_t*,
    CUtensorMapInterleave, CUtensorMapSwizzle, CUtensorMapL2promotion,
    CUtensorMapFloatOOBfill);

extern "C" void kernel_launch(void* const* d_in, const int* in_sizes, int n_in,
                              void* d_out, int out_size)
{
    const float* X      = (const float*)d_in[0];   // [B, D, 4] f32
    const float* params = (const float*)d_in[1];   // [D, 16, 64] f32
    float*       out    = (float*)d_out;           // [B, D, 64] f32

    // Resolve cuTensorMapEncodeTiled without a link-time libcuda dependency.
    EncodeTiledFn encode = nullptr;
    void* h = dlopen("libcuda.so.1", RTLD_LAZY | RTLD_GLOBAL);
    if (!h) h = dlopen("libcuda.so", RTLD_LAZY | RTLD_GLOBAL);
    if (h)  encode = (EncodeTiledFn)dlsym(h, "cuTensorMapEncodeTiled");

    bool tma_ok = false;
    CUtensorMap tmap;
    if (encode) {
        // out viewed as 3D: dim0 = 64 f32 (contiguous), dim1 = D, dim2 = B.
        cuuint64_t dims[3]    = {64, (cuuint64_t)D_DIM, (cuuint64_t)B_DIM};
        cuuint64_t strides[2] = {64ull * 4ull,                       // 256 B
                                 (cuuint64_t)D_DIM * 64ull * 4ull};  // 128 KB
        cuuint32_t box[3]     = {64, 1, T_BCHUNK};
        cuuint32_t estr[3]    = {1, 1, 1};
        tma_ok = (encode(&tmap, CU_TENSOR_MAP_DATA_TYPE_FLOAT32, 3, (void*)out,
                         dims, strides, box, estr,
                         CU_TENSOR_MAP_INTERLEAVE_NONE,
                         CU_TENSOR_MAP_SWIZZLE_NONE,
                         CU_TENSOR_MAP_L2_PROMOTION_L2_128B,
                         CU_TENSOR_MAP_FLOAT_OOB_FILL_NONE) == CUDA_SUCCESS);
    }

    if (tma_ok) {
        dim3 grid(B_DIM / T_BCHUNK, D_DIM);        // (16, 512) = 8192 blocks
        hoa_tma_kernel<<<grid, T_THREADS>>>(X, params, tmap);
    } else {
        dim3 grid(B_DIM / F_BCHUNK, D_DIM);        // (8, 512) = 4096 blocks
        hoa_kernel<<<grid, F_THREADS>>>(X, params, out);
    }
}

// round 14
// speedup vs baseline: 1.1827x; 1.1827x over previous
#include <cuda_runtime.h>
#include <cuda_bf16.h>
#include <cstdint>

// HighOrderActivation: simplex interpolation over K=4 corners of a 2^4 table.
// X: [B=1024, D=512, 4] f32, params: [D=512, 16, 64] f32, out: [B, D, 64] f32.
//
// out[b,d,:] = c0*T[15] + c1*T[ind1] + c2*T[ind2] + c3*T[ind3]
//   xs = sort(X[b,d,:]), c = [xs0, diffs], ind = reverse bit-cumsum of 1<<idx.
//
// R13 learning: TMA stores share the L1 wavefront path with LDS/STG — no win,
// reverted. R12/R13 both plateau at ~26us with L1~75%, issue~52%, occ~65%
// (regfile-capped at 48 warps). This round: SAME byte flow, fewer registers.
// 16 threads per pair, ONE float4 output slot each -> per-thread live state
// ~32 regs -> 8 CTAs/SM -> 64 warps -> more latency coverage for the 29-cyc
// LDS exposures.
//
// Branchless uint-key sort (IMNMX network, index packed in low mantissa bits,
// ~2e-7 rel err vs 1e-3 gate, stable-argsort tie order) — verified in R12.

#define B_DIM  1024
#define D_DIM  512
#define TBL_ROWS 16
#define BCHUNK 128
#define THREADS_PER_BLOCK 256
#define PAIRS_PER_ITER (THREADS_PER_BLOCK / 16)  // 16
#define ITERS (BCHUNK / PAIRS_PER_ITER)          // 8

// Order-preserving float->uint key with 2-bit index packed in the LSBs.
static __device__ __forceinline__ uint32_t fkey(float f, uint32_t i) {
    uint32_t u = __float_as_uint(f);
    uint32_t m = (uint32_t)((int32_t)u >> 31);          // ~0 if negative
    uint32_t k = u ^ (m | 0x80000000u);
    return (k & ~3u) | i;
}
// Inverse transform (idx bits cleared first).
static __device__ __forceinline__ float fdec(uint32_t k) {
    uint32_t kc = k & ~3u;
    uint32_t m  = (uint32_t)((int32_t)kc >> 31);        // ~0 if originally >= 0
    return __uint_as_float(kc ^ (~m | 0x80000000u));
}

__global__ __launch_bounds__(THREADS_PER_BLOCK, 8)
void hoa_kernel(const float* __restrict__ X,
                const float* __restrict__ params,
                float* __restrict__ out)
{
    __shared__ float4 tab[TBL_ROWS * 16];  // params[d]: 4 KB
    __shared__ float4 xsm[BCHUNK];         // block's X: 2 KB

    const int tid = threadIdx.x;
    const int d   = blockIdx.y;
    const int b0  = blockIdx.x * BCHUNK;

    tab[tid] = reinterpret_cast<const float4*>(params)[(size_t)d * (TBL_ROWS * 16) + tid];
    if (tid < BCHUNK) {
        xsm[tid] = reinterpret_cast<const float4*>(X)[(size_t)(b0 + tid) * D_DIM + d];
    }
    __syncthreads();

    const int o         = tid & 15;   // this thread's float4 slot (0..15)
    const int pair_base = tid >> 4;   // 0..15 within iteration

    // Row 15 (used by every output) cached in registers: one float4 now.
    const float4 r15 = tab[15 * 16 + o];

    #pragma unroll
    for (int it = 0; it < ITERS; ++it) {
        const int pr = it * PAIRS_PER_ITER + pair_base;   // 0..BCHUNK-1
        const size_t p = (size_t)(b0 + pr) * D_DIM + d;

        // Broadcast LDS: 16 threads of a pair read the same 16 B.
        const float4 xv = xsm[pr];

        // Branchless key sort (all four keys independent -> full ILP).
        uint32_t k0 = fkey(xv.x, 0);
        uint32_t k1 = fkey(xv.y, 1);
        uint32_t k2 = fkey(xv.z, 2);
        uint32_t k3 = fkey(xv.w, 3);
#define USWAP(a, b_)                                   \
        do {                                           \
            uint32_t lo = min(a, b_);                  \
            uint32_t hi = max(a, b_);                  \
            a = lo; b_ = hi;                           \
        } while (0)
        USWAP(k0, k1);
        USWAP(k2, k3);
        USWAP(k0, k2);
        USWAP(k1, k3);
        USWAP(k1, k2);
#undef USWAP

        const float v0 = fdec(k0);
        const float v1 = fdec(k1);
        const float v2 = fdec(k2);
        const float v3 = fdec(k3);
        const int   i0 = (int)(k0 & 3u);
        const int   i1 = (int)(k1 & 3u);
        const int   i3 = (int)(k3 & 3u);

        // Corner indices (ind0 == 15 always, served from regs).
        const int ind1 = 15 - (1 << i0);
        const int ind2 = ind1 - (1 << i1);
        const int ind3 = (1 << i3);

        // Simplex coefficients.
        const float c0 = v0;
        const float c1 = v1 - v0;
        const float c2 = v2 - v1;
        const float c3 = v3 - v2;

        // Gather 3 rows x 1 slot from smem (LDS.128; quarter-warp groups each
        // read 128 B contiguous -> conflict-free).
        const float4 g1 = tab[ind1 * 16 + o];
        const float4 g2 = tab[ind2 * 16 + o];
        const float4 g3 = tab[ind3 * 16 + o];

        float4 r;
        r.x = c0 * r15.x + c1 * g1.x + c2 * g2.x + c3 * g3.x;
        r.y = c0 * r15.y + c1 * g1.y + c2 * g2.y + c3 * g3.y;
        r.z = c0 * r15.z + c1 * g1.z + c2 * g2.z + c3 * g3.z;
        r.w = c0 * r15.w + c1 * g1.w + c2 * g2.w + c3 * g3.w;

        // One STG.E.128; the 16 threads of a pair cover the 256 B output row
        // as two fully-coalesced 128 B segments.
        reinterpret_cast<float4*>(out)[p * 16 + o] = r;
    }
}

extern "C" void kernel_launch(void* const* d_in, const int* in_sizes, int n_in,
                              void* d_out, int out_size)
{
    const float* X      = (const float*)d_in[0];   // [B, D, 4] f32
    const float* params = (const float*)d_in[1];   // [D, 16, 64] f32
    float*       out    = (float*)d_out;           // [B, D, 64] f32

    dim3 grid(B_DIM / BCHUNK, D_DIM);              // (8, 512) = 4096 blocks
    hoa_kernel<<<grid, THREADS_PER_BLOCK>>>(X, params, out);
}

// round 15
// speedup vs baseline: 1.3502x; 1.1416x over previous
#include <cuda_runtime.h>
#include <cuda_bf16.h>
#include <cstdint>

// HighOrderActivation: simplex interpolation over K=4 corners of a 2^4 table.
// X: [B=1024, D=512, 4] f32, params: [D=512, 16, 64] f32, out: [B, D, 64] f32.
//
// out[b,d,:] = c0*T[15] + c1*T[ind1] + c2*T[ind2] + c3*T[ind3]
//   xs = sort(X[b,d,:]), c = [xs0, diffs], ind = reverse bit-cumsum of 1<<idx.
//
// Model (validated over R12-R14): limiter is L1 wavefront throughput
// (LDS gathers + STG share it; floor ~19us, R12 ran at 74.7% = 26us), with
// the gap being latency coverage (occ 65%, 40 regs). R14 proved occupancy
// helps only if ALU redundancy stays low (8 thr/pair, not 16).
// This round: R12's mapping (8 thr/pair, 2 slots) with SLOT-SERIAL
// processing to halve gather liveness -> <=36 regs -> 7 CTAs/SM (56 warps).
//
// Branchless uint-key sort (IMNMX network, index in low mantissa bits,
// rel_err ~2e-7 vs 1e-3 gate, stable-argsort ties) — verified R12.

#define B_DIM  1024
#define D_DIM  512
#define TBL_ROWS 16
#define BCHUNK 128
#define THREADS_PER_BLOCK 256
#define PAIRS_PER_ITER (THREADS_PER_BLOCK / 8)   // 32
#define ITERS (BCHUNK / PAIRS_PER_ITER)          // 4

// Order-preserving float->uint key with 2-bit index packed in the LSBs.
static __device__ __forceinline__ uint32_t fkey(float f, uint32_t i) {
    uint32_t u = __float_as_uint(f);
    uint32_t m = (uint32_t)((int32_t)u >> 31);          // ~0 if negative
    uint32_t k = u ^ (m | 0x80000000u);
    return (k & ~3u) | i;
}
// Inverse transform (idx bits cleared first).
static __device__ __forceinline__ float fdec(uint32_t k) {
    uint32_t kc = k & ~3u;
    uint32_t m  = (uint32_t)((int32_t)kc >> 31);        // ~0 if originally >= 0
    return __uint_as_float(kc ^ (~m | 0x80000000u));
}

__global__ __launch_bounds__(THREADS_PER_BLOCK, 7)
void hoa_kernel(const float* __restrict__ X,
                const float* __restrict__ params,
                float* __restrict__ out)
{
    __shared__ float4 tab[TBL_ROWS * 16];  // params[d]: 4 KB
    __shared__ float4 xsm[BCHUNK];         // block's X: 2 KB

    const int tid = threadIdx.x;
    const int d   = blockIdx.y;
    const int b0  = blockIdx.x * BCHUNK;

    tab[tid] = reinterpret_cast<const float4*>(params)[(size_t)d * (TBL_ROWS * 16) + tid];
    if (tid < BCHUNK) {
        xsm[tid] = reinterpret_cast<const float4*>(X)[(size_t)(b0 + tid) * D_DIM + d];
    }
    __syncthreads();

    const int o         = tid & 7;    // float4 slots o and o+8
    const int pair_base = tid >> 3;   // 0..31 within iteration

    // Row 15 (used by every output) cached in registers.
    const float4 r15a = tab[15 * 16 + o];
    const float4 r15b = tab[15 * 16 + o + 8];

    #pragma unroll
    for (int it = 0; it < ITERS; ++it) {
        const int pr = it * PAIRS_PER_ITER + pair_base;
        const size_t p = (size_t)(b0 + pr) * D_DIM + d;

        // Broadcast LDS: 8 threads of a pair read the same 16 B.
        const float4 xv = xsm[pr];

        // Branchless key sort (four independent keys -> full ILP).
        uint32_t k0 = fkey(xv.x, 0);
        uint32_t k1 = fkey(xv.y, 1);
        uint32_t k2 = fkey(xv.z, 2);
        uint32_t k3 = fkey(xv.w, 3);
#define USWAP(a, b_)                                   \
        do {                                           \
            uint32_t lo = min(a, b_);                  \
            uint32_t hi = max(a, b_);                  \
            a = lo; b_ = hi;                           \
        } while (0)
        USWAP(k0, k1);
        USWAP(k2, k3);
        USWAP(k0, k2);
        USWAP(k1, k3);
        USWAP(k1, k2);
#undef USWAP

        const float v0 = fdec(k0);
        const float v1 = fdec(k1);
        const float v2 = fdec(k2);
        const float v3 = fdec(k3);
        const int   i0 = (int)(k0 & 3u);
        const int   i1 = (int)(k1 & 3u);
        const int   i3 = (int)(k3 & 3u);

        // Corner indices (ind0 == 15 always, served from regs).
        const int ind1 = 15 - (1 << i0);
        const int ind2 = ind1 - (1 << i1);
        const int ind3 = (1 << i3);

        // Simplex coefficients.
        const float c0 = v0;
        const float c1 = v1 - v0;
        const float c2 = v2 - v1;
        const float c3 = v3 - v2;

        float4* orow = reinterpret_cast<float4*>(out) + p * 16;

        // ---- slot A: gather -> FMA -> store (low register liveness) ----
        {
            const float4 g1 = tab[ind1 * 16 + o];
            const float4 g2 = tab[ind2 * 16 + o];
            const float4 g3 = tab[ind3 * 16 + o];
            float4 r;
            r.x = c0 * r15a.x + c1 * g1.x + c2 * g2.x + c3 * g3.x;
            r.y = c0 * r15a.y + c1 * g1.y + c2 * g2.y + c3 * g3.y;
            r.z = c0 * r15a.z + c1 * g1.z + c2 * g2.z + c3 * g3.z;
            r.w = c0 * r15a.w + c1 * g1.w + c2 * g2.w + c3 * g3.w;
            orow[o] = r;
        }
        // ---- slot B ----
        {
            const float4 g1 = tab[ind1 * 16 + o + 8];
            const float4 g2 = tab[ind2 * 16 + o + 8];
            const float4 g3 = tab[ind3 * 16 + o + 8];
            float4 r;
            r.x = c0 * r15b.x + c1 * g1.x + c2 * g2.x + c3 * g3.x;
            r.y = c0 * r15b.y + c1 * g1.y + c2 * g2.y + c3 * g3.y;
            r.z = c0 * r15b.z + c1 * g1.z + c2 * g2.z + c3 * g3.z;
            r.w = c0 * r15b.w + c1 * g1.w + c2 * g2.w + c3 * g3.w;
            orow[o + 8] = r;
        }
    }
}

extern "C" void kernel_launch(void* const* d_in, const int* in_sizes, int n_in,
                              void* d_out, int out_size)
{
    const float* X      = (const float*)d_in[0];   // [B, D, 4] f32
    const float* params = (const float*)d_in[1];   // [D, 16, 64] f32
    float*       out    = (float*)d_out;           // [B, D, 64] f32

    dim3 grid(B_DIM / BCHUNK, D_DIM);              // (8, 512) = 4096 blocks
    hoa_kernel<<<grid, THREADS_PER_BLOCK>>>(X, params, out);
}